// round 9
// baseline (speedup 1.0000x reference)
#include <cuda_runtime.h>
#include <cuda_bf16.h>
#include <cstdint>

#define NN 16384
#define KN 25
#define DD 256
#define LL 64
#define NPC 2                   // nodes per CTA
#define ROWS (NPC * KN)         // 50
#define MM 64                   // padded MMA M
#define NCTA (NN / NPC)         // 8192 (exact)
#define ASTRIDE 72              // A smem row stride in bf16 elems (conflict-free)
#define DBS 132                 // dbuf row stride (floats)

// device scratch (no allocation allowed)
__device__ float g_expected[NN * DD];
__device__ unsigned short g_Bhi[DD * LL];   // [d][l] = bf16_hi(W_link[l][d])
__device__ unsigned short g_Blo[DD * LL];
__device__ float g_ts[NN];

typedef unsigned int uint;
typedef unsigned long long ull;

// ---------------- smem layout (byte offsets in dynamic smem) ---------------
#define NEIGH_OFF   0           // 50*256*4      = 51200
#define A_HI_OFF    51200       // 64*72*2       = 9216
#define A_LO_OFF    60416       // 9216
#define DBUF_OFF    69632       // 64*132*4      = 33792
#define TLINK_OFF   103424      // 64*4
#define TNEIGH_OFF  103680      // 64*4
#define WK_OFF      103936      // 64*4
#define GNW_OFF     104192      // 256*4
#define GLW_OFF     105216      // 64*4
#define SMEM_TOTAL  105472      // ~103 KB -> 2 CTAs/SM

__device__ __forceinline__ uint pkbf(__nv_bfloat16 a, __nv_bfloat16 b) {
    return ((uint)__bfloat16_as_ushort(b) << 16) | (uint)__bfloat16_as_ushort(a);
}
__device__ __forceinline__ float sigm_fast(float x) {  // 1 MUFU (tanh.approx)
    float th;
    asm("tanh.approx.f32 %0, %1;" : "=f"(th) : "f"(0.5f * x));
    return fmaf(0.5f, th, 0.5f);
}
// m16n8k16 bf16 mma, f32 accum (base-target PTX, runs on fallback HMMA)
__device__ __forceinline__ void mma_bf16(float* c, const uint* a, uint b0, uint b1) {
    asm volatile(
        "mma.sync.aligned.m16n8k16.row.col.f32.bf16.bf16.f32 "
        "{%0,%1,%2,%3}, {%4,%5,%6,%7}, {%8,%9}, {%0,%1,%2,%3};"
        : "+f"(c[0]), "+f"(c[1]), "+f"(c[2]), "+f"(c[3])
        : "r"(a[0]), "r"(a[1]), "r"(a[2]), "r"(a[3]), "r"(b0), "r"(b1));
}

// ---------------------------------------------------------------------------
// Precursor 1: split-transpose W_link -> g_Bhi/g_Blo (bf16 hi/lo, [d][l])
// ---------------------------------------------------------------------------
__global__ void conv_w_kernel(const float* __restrict__ W_link) {
    int idx = blockIdx.x * 256 + threadIdx.x;   // 0..16383
    int l = idx >> 8, d = idx & 255;
    float x = W_link[idx];
    __nv_bfloat16 h = __float2bfloat16(x);
    float r = x - __bfloat162float(h);
    g_Bhi[d * LL + l] = __bfloat16_as_ushort(h);
    g_Blo[d * LL + l] = __bfloat16_as_ushort(__float2bfloat16(r));
}

// Precursor 2: g_ts[n] = self_vecs[n] . g_self_w
__global__ void ts_kernel(const float* __restrict__ self_vecs,
                          const float* __restrict__ g_self_w) {
    int warp = (blockIdx.x * 256 + threadIdx.x) >> 5;   // 512 warps
    int lane = threadIdx.x & 31;
    for (int n = warp; n < NN; n += 512) {
        float s = 0.f;
#pragma unroll
        for (int q = 0; q < 8; q++) {
            int d = lane + 32 * q;
            s = fmaf(self_vecs[n * DD + d], g_self_w[d], s);
        }
#pragma unroll
        for (int o = 16; o > 0; o >>= 1) s += __shfl_xor_sync(0xffffffffu, s, o);
        if (lane == 0) g_ts[n] = s;
    }
}

// ---------------------------------------------------------------------------
// Kernel A: per CTA = 2 nodes (50 rows padded to M=64).
//   S[64,256] = link[64,64] @ W_link via warp-level bf16 mma (3-term split),
//   computed in TWO 128-column passes so each warp's accumulator set is
//   acc[4][2][4] = 32 regs (no spills under the 128-reg/2-CTA bound).
//   Per pass: sigmoid(S)*wk -> dbuf, then reduce over k for those 128 cols.
// ---------------------------------------------------------------------------
__global__ __launch_bounds__(256, 2) void mma_agg_kernel(
    const float* __restrict__ neigh_vecs,
    const float* __restrict__ link_vecs,
    const float* __restrict__ select_probs,
    const float* __restrict__ g_neigh_w,
    const float* __restrict__ g_link_w)
{
    extern __shared__ char sm[];
    const int t    = threadIdx.x;
    const int wid  = t >> 5;
    const int lane = t & 31;
    const int g8   = lane >> 2;     // mma groupID (0..7)
    const int tig  = lane & 3;      // thread-in-group
    const int b    = blockIdx.x;

    float*  neigh_s  = (float*)(sm + NEIGH_OFF);
    unsigned short* Ahi = (unsigned short*)(sm + A_HI_OFF);
    unsigned short* Alo = (unsigned short*)(sm + A_LO_OFF);
    float*  dbuf     = (float*)(sm + DBUF_OFF);
    float*  tlink_s  = (float*)(sm + TLINK_OFF);
    float*  tneigh_s = (float*)(sm + TNEIGH_OFF);
    float*  wk_s     = (float*)(sm + WK_OFF);
    float*  gnw_s    = (float*)(sm + GNW_OFF);
    float*  glw_s    = (float*)(sm + GLW_OFF);

    // step 0: small vectors + zero wk padding rows
    gnw_s[t] = g_neigh_w[t];
    if (t < LL) glw_s[t] = g_link_w[t];
    if (t < MM) wk_s[t] = 0.f;
    __syncthreads();

    // step 1a: stage neigh tile [50,256] f32 (contiguous float4, coalesced)
    {
        const float4* src = (const float4*)(neigh_vecs + (long)b * ROWS * DD);
        for (int idx = t; idx < (ROWS * DD) / 4; idx += 256)
            ((float4*)neigh_s)[idx] = src[idx];
    }

    // step 1b: stage A hi/lo bf16 [64, ASTRIDE] + tlink partial dots
    {
        int r = t >> 2, q = t & 3;              // row, 16-elem quarter
        bool valid = r < ROWS;
        const float4* src = (const float4*)(link_vecs + ((long)b * ROWS + r) * LL + 16 * q);
        const float4 z4 = make_float4(0.f, 0.f, 0.f, 0.f);
        uint hs[8], ls[8];
        float dl = 0.f;
#pragma unroll
        for (int u = 0; u < 4; u++) {
            float4 x = valid ? src[u] : z4;
            __nv_bfloat16 hx = __float2bfloat16(x.x), hy = __float2bfloat16(x.y);
            __nv_bfloat16 hz = __float2bfloat16(x.z), hw = __float2bfloat16(x.w);
            hs[2*u]   = pkbf(hx, hy);
            hs[2*u+1] = pkbf(hz, hw);
            ls[2*u]   = pkbf(__float2bfloat16(x.x - __bfloat162float(hx)),
                             __float2bfloat16(x.y - __bfloat162float(hy)));
            ls[2*u+1] = pkbf(__float2bfloat16(x.z - __bfloat162float(hz)),
                             __float2bfloat16(x.w - __bfloat162float(hw)));
            int lb = 16 * q + 4 * u;
            dl = fmaf(x.x, glw_s[lb],     dl);
            dl = fmaf(x.y, glw_s[lb + 1], dl);
            dl = fmaf(x.z, glw_s[lb + 2], dl);
            dl = fmaf(x.w, glw_s[lb + 3], dl);
        }
        int eo = r * ASTRIDE + 16 * q;          // element offset
        *(uint4*)&Ahi[eo]     = make_uint4(hs[0], hs[1], hs[2], hs[3]);
        *(uint4*)&Ahi[eo + 8] = make_uint4(hs[4], hs[5], hs[6], hs[7]);
        *(uint4*)&Alo[eo]     = make_uint4(ls[0], ls[1], ls[2], ls[3]);
        *(uint4*)&Alo[eo + 8] = make_uint4(ls[4], ls[5], ls[6], ls[7]);
        dl += __shfl_xor_sync(0xffffffffu, dl, 1);
        dl += __shfl_xor_sync(0xffffffffu, dl, 2);
        if (q == 0 && valid) tlink_s[r] = dl;
    }
    __syncthreads();

    // step 2: gate — trans_neigh warp-task dots
    for (int task = wid; task < ROWS; task += 8) {
        float s = 0.f;
#pragma unroll
        for (int q = 0; q < 8; q++) {
            int d = lane + 32 * q;
            s = fmaf(neigh_s[task * DD + d], gnw_s[d], s);
        }
#pragma unroll
        for (int o = 16; o > 0; o >>= 1) s += __shfl_xor_sync(0xffffffffu, s, o);
        if (lane == 0) tneigh_s[task] = s;
    }
    __syncthreads();
    if (t < ROWS) {
        int node = t / KN, k = t - node * KN;
        int n = b * NPC + node;
        float r  = g_ts[n] + tneigh_s[t] + tlink_s[t];
        float gt = 1.f / (1.f + __expf(-r));
        wk_s[t]  = gt / (select_probs[n * KN + k] * (float)KN);
    }
    __syncthreads();

    // step 3+4: two 128-column passes. Warp w owns cols [16w, 16w+16) of half.
#pragma unroll
    for (int half = 0; half < 2; half++) {
        float acc[4][2][4];
#pragma unroll
        for (int mi = 0; mi < 4; mi++)
#pragma unroll
            for (int ni = 0; ni < 2; ni++)
#pragma unroll
                for (int j = 0; j < 4; j++) acc[mi][ni][j] = 0.f;

#pragma unroll
        for (int kk = 0; kk < 4; kk++) {
            uint ahi[4][4], alo[4][4];
#pragma unroll
            for (int mi = 0; mi < 4; mi++) {
                int e = (16 * mi + g8) * ASTRIDE + 16 * kk + 2 * tig;
                ahi[mi][0] = *(const uint*)&Ahi[e];
                ahi[mi][1] = *(const uint*)&Ahi[e + 8 * ASTRIDE];
                ahi[mi][2] = *(const uint*)&Ahi[e + 8];
                ahi[mi][3] = *(const uint*)&Ahi[e + 8 * ASTRIDE + 8];
                alo[mi][0] = *(const uint*)&Alo[e];
                alo[mi][1] = *(const uint*)&Alo[e + 8 * ASTRIDE];
                alo[mi][2] = *(const uint*)&Alo[e + 8];
                alo[mi][3] = *(const uint*)&Alo[e + 8 * ASTRIDE + 8];
            }
#pragma unroll
            for (int ni = 0; ni < 2; ni++) {
                int n  = 128 * half + 16 * wid + 8 * ni + g8;  // B col (output d)
                int ke = n * LL + 16 * kk + 2 * tig;           // elem in [d][l]
                uint bh0 = *(const uint*)&g_Bhi[ke];
                uint bh1 = *(const uint*)&g_Bhi[ke + 8];
                uint bl0 = *(const uint*)&g_Blo[ke];
                uint bl1 = *(const uint*)&g_Blo[ke + 8];
#pragma unroll
                for (int mi = 0; mi < 4; mi++) {
                    mma_bf16(acc[mi][ni], ahi[mi], bh0, bh1);
                    mma_bf16(acc[mi][ni], ahi[mi], bl0, bl1);
                    mma_bf16(acc[mi][ni], alo[mi], bh0, bh1);
                }
            }
        }

        // epilogue A: sigmoid * wk -> dbuf[64][DBS] (cols within half)
#pragma unroll
        for (int mi = 0; mi < 4; mi++) {
            int row0 = 16 * mi + g8;
            float w0 = wk_s[row0], w1 = wk_s[row0 + 8];
#pragma unroll
            for (int ni = 0; ni < 2; ni++) {
                int col = 16 * wid + 8 * ni + 2 * tig;
                float2 v0, v1;
                v0.x = sigm_fast(acc[mi][ni][0]) * w0;
                v0.y = sigm_fast(acc[mi][ni][1]) * w0;
                v1.x = sigm_fast(acc[mi][ni][2]) * w1;
                v1.y = sigm_fast(acc[mi][ni][3]) * w1;
                *(float2*)&dbuf[row0 * DBS + col]       = v0;
                *(float2*)&dbuf[(row0 + 8) * DBS + col] = v1;
            }
        }
        __syncthreads();

        // epilogue B: reduce over k for these 128 cols (2 nodes x 128 cols)
        {
            int node = t >> 7, col = t & 127;
            int rb = node * KN;
            float a = 0.f;
#pragma unroll
            for (int j = 0; j < KN; j++)
                a = fmaf(dbuf[(rb + j) * DBS + col],
                         neigh_s[(rb + j) * DD + 128 * half + col], a);
            g_expected[((long)b * NPC + node) * DD + 128 * half + col] = a;
        }
        __syncthreads();
    }
}

// ---------------------------------------------------------------------------
// Kernel B: out[:, coff:coff+256] = relu(A @ W)  (unchanged, proven)
// ---------------------------------------------------------------------------
__device__ __forceinline__ ull pk2(float lo, float hi) {
    ull r; asm("mov.b64 %0, {%1, %2};" : "=l"(r) : "f"(lo), "f"(hi)); return r;
}
__device__ __forceinline__ float2 upk2(ull v) {
    float2 f; asm("mov.b64 {%0, %1}, %2;" : "=f"(f.x), "=f"(f.y) : "l"(v)); return f;
}
__device__ __forceinline__ ull ffma2(ull a, ull b, ull c) {
    ull d; asm("fma.rn.f32x2 %0, %1, %2, %3;" : "=l"(d) : "l"(a), "l"(b), "l"(c)); return d;
}

__global__ __launch_bounds__(256) void gemm_relu_kernel(
    const float* __restrict__ A_in,
    const float* __restrict__ W,
    float* __restrict__ out,
    int coff, int use_expected)
{
    const float* __restrict__ A = use_expected ? (const float*)g_expected : A_in;

    __shared__ float As[64][32];
    __shared__ alignas(16) float Ws[32][64];

    const int tid = threadIdx.x;
    const int tx  = tid & 15;
    const int ty  = tid >> 4;
    const int r0  = blockIdx.x * 64;
    const int c0  = blockIdx.y * 64;

    ull acc[4][2];
#pragma unroll
    for (int i = 0; i < 4; i++) { acc[i][0] = 0ull; acc[i][1] = 0ull; }

    for (int kb = 0; kb < DD; kb += 32) {
#pragma unroll
        for (int u = 0; u < 2; u++) {
            int idx = tid + u * 256;
            int m = idx >> 3, q = idx & 7;
            *(float4*)&As[m][q * 4] =
                *(const float4*)&A[(size_t)(r0 + m) * DD + kb + q * 4];
        }
#pragma unroll
        for (int u = 0; u < 2; u++) {
            int idx = tid + u * 256;
            int kk = idx >> 4, q = idx & 15;
            *(float4*)&Ws[kk][q * 4] =
                *(const float4*)&W[(size_t)(kb + kk) * DD + c0 + q * 4];
        }
        __syncthreads();
#pragma unroll
        for (int kk = 0; kk < 32; kk++) {
            ulonglong2 b2 = *(const ulonglong2*)&Ws[kk][tx * 4];
#pragma unroll
            for (int i = 0; i < 4; i++) {
                float a = As[ty * 4 + i][kk];
                ull aa = pk2(a, a);
                acc[i][0] = ffma2(aa, b2.x, acc[i][0]);
                acc[i][1] = ffma2(aa, b2.y, acc[i][1]);
            }
        }
        __syncthreads();
    }

#pragma unroll
    for (int i = 0; i < 4; i++) {
        float2 r01 = upk2(acc[i][0]);
        float2 r23 = upk2(acc[i][1]);
        float4 o;
        o.x = fmaxf(r01.x, 0.f);
        o.y = fmaxf(r01.y, 0.f);
        o.z = fmaxf(r23.x, 0.f);
        o.w = fmaxf(r23.y, 0.f);
        *(float4*)&out[(size_t)(r0 + ty * 4 + i) * 512 + coff + c0 + tx * 4] = o;
    }
}

extern "C" void kernel_launch(void* const* d_in, const int* in_sizes, int n_in,
                              void* d_out, int out_size)
{
    const float* self_vecs    = (const float*)d_in[0];
    const float* neigh_vecs   = (const float*)d_in[1];
    const float* link_vecs    = (const float*)d_in[2];
    const float* select_probs = (const float*)d_in[3];
    const float* g_self_w     = (const float*)d_in[4];
    const float* g_neigh_w    = (const float*)d_in[5];
    const float* g_link_w     = (const float*)d_in[6];
    const float* W_link       = (const float*)d_in[7];
    const float* W_self       = (const float*)d_in[8];
    const float* W_neigh      = (const float*)d_in[9];
    float* out = (float*)d_out;

    static int attr_set = 0;
    if (!attr_set) {
        cudaFuncSetAttribute(mma_agg_kernel,
                             cudaFuncAttributeMaxDynamicSharedMemorySize, SMEM_TOTAL);
        attr_set = 1;
    }

    conv_w_kernel<<<64, 256>>>(W_link);
    ts_kernel<<<64, 256>>>(self_vecs, g_self_w);

    mma_agg_kernel<<<NCTA, 256, SMEM_TOTAL>>>(neigh_vecs, link_vecs, select_probs,
                                              g_neigh_w, g_link_w);

    dim3 g(NN / 64, 256 / 64);
    gemm_relu_kernel<<<g, 256>>>(self_vecs, W_self, out, 0, 0);
    gemm_relu_kernel<<<g, 256>>>(nullptr, W_neigh, out, 256, 1);
}

// round 10
// speedup vs baseline: 1.6519x; 1.6519x over previous
#include <cuda_runtime.h>
#include <cuda_bf16.h>
#include <cstdint>

#define NN 16384
#define KN 25
#define DD 256
#define LL 64
#define NPC 2                   // nodes per CTA
#define ROWS (NPC * KN)         // 50
#define MM 64                   // padded MMA M
#define NCTA (NN / NPC)         // 8192 (exact)
#define AST 68                  // A smem row stride in u32 (68 % 32 == 4 -> conflict-free frags)

// device scratch (no allocation allowed)
__device__ float g_expected[NN * DD];
__device__ uint2 g_Bfrag[DD * 8 * 4];   // [n][kk][tig] = {B[8kk+tig][n], B[8kk+tig+4][n]} as tf32
__device__ float g_ts[NN];

typedef unsigned int uint;
typedef unsigned long long ull;

// ---------------- smem layout (byte offsets in dynamic smem) ---------------
#define NEIGH_OFF   0           // 50*256*4  = 51200
#define A_OFF       51200       // 64*68*4   = 17408 (tf32)
#define DBUF_OFF    68608       // 32*260*4  = 33280
#define EXP_OFF     101888      // 2*256*4   = 2048
#define TLINK_OFF   103936      // 64*4
#define TNEIGH_OFF  104192      // 64*4
#define WK_OFF      104448      // 64*4
#define GNW_OFF     104704      // 256*4
#define GLW_OFF     105728      // 64*4
#define SMEM_TOTAL  105984      // ~103.5 KB -> 2 CTAs/SM

__device__ __forceinline__ uint tf32r(float x) {   // round-to-nearest tf32
    uint r; asm("cvt.rna.tf32.f32 %0, %1;" : "=r"(r) : "f"(x)); return r;
}
__device__ __forceinline__ float sigm_fast(float x) {  // 1 MUFU (tanh.approx)
    float th;
    asm("tanh.approx.f32 %0, %1;" : "=f"(th) : "f"(0.5f * x));
    return fmaf(0.5f, th, 0.5f);
}
// m16n8k8 tf32 mma, f32 accum (base-target PTX, sm_80+)
__device__ __forceinline__ void mma_tf32(float* c, const uint* a, uint b0, uint b1) {
    asm volatile(
        "mma.sync.aligned.m16n8k8.row.col.f32.tf32.tf32.f32 "
        "{%0,%1,%2,%3}, {%4,%5,%6,%7}, {%8,%9}, {%0,%1,%2,%3};"
        : "+f"(c[0]), "+f"(c[1]), "+f"(c[2]), "+f"(c[3])
        : "r"(a[0]), "r"(a[1]), "r"(a[2]), "r"(a[3]), "r"(b0), "r"(b1));
}

// ---------------------------------------------------------------------------
// Precursor 1: pre-pack W_link into tf32 B-fragments in mma lane order.
//   g_Bfrag[((n*8 + kk)*4 + tig)] = { tf32(W[8kk+tig][n]), tf32(W[8kk+tig+4][n]) }
// ---------------------------------------------------------------------------
__global__ void conv_w_kernel(const float* __restrict__ W_link) {
    int idx = blockIdx.x * 256 + threadIdx.x;   // 0..8191
    int n   = idx >> 5;
    int kk  = (idx >> 2) & 7;
    int tig = idx & 3;
    int l0  = 8 * kk + tig;
    uint2 v;
    v.x = tf32r(W_link[l0 * DD + n]);
    v.y = tf32r(W_link[(l0 + 4) * DD + n]);
    g_Bfrag[idx] = v;
}

// Precursor 2: g_ts[n] = self_vecs[n] . g_self_w
__global__ void ts_kernel(const float* __restrict__ self_vecs,
                          const float* __restrict__ g_self_w) {
    int warp = (blockIdx.x * 256 + threadIdx.x) >> 5;   // 512 warps
    int lane = threadIdx.x & 31;
    for (int n = warp; n < NN; n += 512) {
        float s = 0.f;
#pragma unroll
        for (int q = 0; q < 8; q++) {
            int d = lane + 32 * q;
            s = fmaf(self_vecs[n * DD + d], g_self_w[d], s);
        }
#pragma unroll
        for (int o = 16; o > 0; o >>= 1) s += __shfl_xor_sync(0xffffffffu, s, o);
        if (lane == 0) g_ts[n] = s;
    }
}

// ---------------------------------------------------------------------------
// Kernel A: per CTA = 2 nodes (50 rows padded to M=64).
//   S[64,256] = link[64,64] @ W_link via single-pass tf32 m16n8k8 mma
//   (3x less tensor work than the bf16 3-term split; tf32 error ~1e-4 rel,
//   well inside the 1e-3 gate). B operands pre-packed in fragment order.
//   Gate + epilogue identical to the proven R7 kernel.
// ---------------------------------------------------------------------------
__global__ __launch_bounds__(256, 2) void mma_agg_kernel(
    const float* __restrict__ neigh_vecs,
    const float* __restrict__ link_vecs,
    const float* __restrict__ select_probs,
    const float* __restrict__ g_neigh_w,
    const float* __restrict__ g_link_w)
{
    extern __shared__ char sm[];
    const int t    = threadIdx.x;
    const int wid  = t >> 5;
    const int lane = t & 31;
    const int g8   = lane >> 2;     // mma groupID (0..7)
    const int tig  = lane & 3;      // thread-in-group
    const int b    = blockIdx.x;

    float*  neigh_s  = (float*)(sm + NEIGH_OFF);
    uint*   Asm      = (uint*)(sm + A_OFF);
    float*  dbuf     = (float*)(sm + DBUF_OFF);
    float*  exp_s    = (float*)(sm + EXP_OFF);
    float*  tlink_s  = (float*)(sm + TLINK_OFF);
    float*  tneigh_s = (float*)(sm + TNEIGH_OFF);
    float*  wk_s     = (float*)(sm + WK_OFF);
    float*  gnw_s    = (float*)(sm + GNW_OFF);
    float*  glw_s    = (float*)(sm + GLW_OFF);

    // step 0: small vectors + zero init
    gnw_s[t] = g_neigh_w[t];
    if (t < LL) glw_s[t] = g_link_w[t];
    if (t < MM) wk_s[t] = 0.f;
    exp_s[t] = 0.f; exp_s[256 + t] = 0.f;
    __syncthreads();

    // step 1a: stage neigh tile [50,256] f32 (contiguous float4, coalesced)
    {
        const float4* src = (const float4*)(neigh_vecs + (long)b * ROWS * DD);
        for (int idx = t; idx < (ROWS * DD) / 4; idx += 256)
            ((float4*)neigh_s)[idx] = src[idx];
    }

    // step 1b: stage A as tf32 [64, AST] + tlink partial dots
    {
        int r = t >> 2, q = t & 3;              // row, 16-elem quarter
        bool valid = r < ROWS;
        const float4* src = (const float4*)(link_vecs + ((long)b * ROWS + r) * LL + 16 * q);
        const float4 z4 = make_float4(0.f, 0.f, 0.f, 0.f);
        float dl = 0.f;
#pragma unroll
        for (int u = 0; u < 4; u++) {
            float4 x = valid ? src[u] : z4;
            uint4 c4 = make_uint4(tf32r(x.x), tf32r(x.y), tf32r(x.z), tf32r(x.w));
            *(uint4*)&Asm[r * AST + 16 * q + 4 * u] = c4;
            int lb = 16 * q + 4 * u;
            dl = fmaf(x.x, glw_s[lb],     dl);
            dl = fmaf(x.y, glw_s[lb + 1], dl);
            dl = fmaf(x.z, glw_s[lb + 2], dl);
            dl = fmaf(x.w, glw_s[lb + 3], dl);
        }
        dl += __shfl_xor_sync(0xffffffffu, dl, 1);
        dl += __shfl_xor_sync(0xffffffffu, dl, 2);
        if (q == 0 && valid) tlink_s[r] = dl;
    }
    __syncthreads();

    // step 2: gate — trans_neigh warp-task dots
    for (int task = wid; task < ROWS; task += 8) {
        float s = 0.f;
#pragma unroll
        for (int q = 0; q < 8; q++) {
            int d = lane + 32 * q;
            s = fmaf(neigh_s[task * DD + d], gnw_s[d], s);
        }
#pragma unroll
        for (int o = 16; o > 0; o >>= 1) s += __shfl_xor_sync(0xffffffffu, s, o);
        if (lane == 0) tneigh_s[task] = s;
    }
    __syncthreads();
    if (t < ROWS) {
        int node = t / KN, k = t - node * KN;
        int n = b * NPC + node;
        float r  = g_ts[n] + tneigh_s[t] + tlink_s[t];
        float gt = 1.f / (1.f + __expf(-r));
        wk_s[t]  = gt / (select_probs[n * KN + k] * (float)KN);
    }
    __syncthreads();

    // step 3: mma  S[64,256] = A[64,64] @ B[64,256]; warp w owns cols [32w,32w+32)
    float acc[4][4][4];
#pragma unroll
    for (int mi = 0; mi < 4; mi++)
#pragma unroll
        for (int ni = 0; ni < 4; ni++)
#pragma unroll
            for (int j = 0; j < 4; j++) acc[mi][ni][j] = 0.f;

#pragma unroll
    for (int kk = 0; kk < 8; kk++) {
        uint af[4][4];
#pragma unroll
        for (int mi = 0; mi < 4; mi++) {
            int e = (16 * mi + g8) * AST + 8 * kk + tig;
            af[mi][0] = Asm[e];
            af[mi][1] = Asm[e + 8 * AST];
            af[mi][2] = Asm[e + 4];
            af[mi][3] = Asm[e + 8 * AST + 4];
        }
#pragma unroll
        for (int ni = 0; ni < 4; ni++) {
            int n = 32 * wid + 8 * ni + g8;           // B col (output d)
            uint2 bb = g_Bfrag[(n * 8 + kk) * 4 + tig];
#pragma unroll
            for (int mi = 0; mi < 4; mi++)
                mma_tf32(acc[mi][ni], af[mi], bb.x, bb.y);
        }
    }

    // step 4: epilogue in two 32-row chunks (identical to proven R7)
#pragma unroll
    for (int c = 0; c < 2; c++) {
#pragma unroll
        for (int mi = 0; mi < 4; mi++) {
            if ((mi >> 1) == c) {
                int mm2  = mi & 1;
                int row0 = 16 * mi + g8;
                float w0 = wk_s[row0], w1 = wk_s[row0 + 8];
#pragma unroll
                for (int ni = 0; ni < 4; ni++) {
                    int col = 32 * wid + 8 * ni + 2 * tig;
                    float2 v0, v1;
                    v0.x = sigm_fast(acc[mi][ni][0]) * w0;
                    v0.y = sigm_fast(acc[mi][ni][1]) * w0;
                    v1.x = sigm_fast(acc[mi][ni][2]) * w1;
                    v1.y = sigm_fast(acc[mi][ni][3]) * w1;
                    *(float2*)&dbuf[(16 * mm2 + g8) * 260 + col]     = v0;
                    *(float2*)&dbuf[(16 * mm2 + g8 + 8) * 260 + col] = v1;
                }
            }
        }
        __syncthreads();
        int r0 = 32 * c;
#pragma unroll
        for (int i = 0; i < NPC; i++) {
            int lo = KN * i > r0 ? KN * i : r0;
            int hi = KN * i + KN < r0 + 32 ? KN * i + KN : r0 + 32;
            float a = 0.f;
            for (int j = lo; j < hi; j++)
                a = fmaf(dbuf[(j - r0) * 260 + t], neigh_s[j * DD + t], a);
            exp_s[i * DD + t] += a;
        }
        __syncthreads();
    }

    // step 5: write expected
#pragma unroll
    for (int i = 0; i < NPC; i++)
        g_expected[((long)b * NPC + i) * DD + t] = exp_s[i * DD + t];
}

// ---------------------------------------------------------------------------
// Kernel B: out[:, coff:coff+256] = relu(A @ W)  (unchanged, proven)
// ---------------------------------------------------------------------------
__device__ __forceinline__ ull pk2(float lo, float hi) {
    ull r; asm("mov.b64 %0, {%1, %2};" : "=l"(r) : "f"(lo), "f"(hi)); return r;
}
__device__ __forceinline__ float2 upk2(ull v) {
    float2 f; asm("mov.b64 {%0, %1}, %2;" : "=f"(f.x), "=f"(f.y) : "l"(v)); return f;
}
__device__ __forceinline__ ull ffma2(ull a, ull b, ull c) {
    ull d; asm("fma.rn.f32x2 %0, %1, %2, %3;" : "=l"(d) : "l"(a), "l"(b), "l"(c)); return d;
}

__global__ __launch_bounds__(256) void gemm_relu_kernel(
    const float* __restrict__ A_in,
    const float* __restrict__ W,
    float* __restrict__ out,
    int coff, int use_expected)
{
    const float* __restrict__ A = use_expected ? (const float*)g_expected : A_in;

    __shared__ float As[64][32];
    __shared__ alignas(16) float Ws[32][64];

    const int tid = threadIdx.x;
    const int tx  = tid & 15;
    const int ty  = tid >> 4;
    const int r0  = blockIdx.x * 64;
    const int c0  = blockIdx.y * 64;

    ull acc[4][2];
#pragma unroll
    for (int i = 0; i < 4; i++) { acc[i][0] = 0ull; acc[i][1] = 0ull; }

    for (int kb = 0; kb < DD; kb += 32) {
#pragma unroll
        for (int u = 0; u < 2; u++) {
            int idx = tid + u * 256;
            int m = idx >> 3, q = idx & 7;
            *(float4*)&As[m][q * 4] =
                *(const float4*)&A[(size_t)(r0 + m) * DD + kb + q * 4];
        }
#pragma unroll
        for (int u = 0; u < 2; u++) {
            int idx = tid + u * 256;
            int kk = idx >> 4, q = idx & 15;
            *(float4*)&Ws[kk][q * 4] =
                *(const float4*)&W[(size_t)(kb + kk) * DD + c0 + q * 4];
        }
        __syncthreads();
#pragma unroll
        for (int kk = 0; kk < 32; kk++) {
            ulonglong2 b2 = *(const ulonglong2*)&Ws[kk][tx * 4];
#pragma unroll
            for (int i = 0; i < 4; i++) {
                float a = As[ty * 4 + i][kk];
                ull aa = pk2(a, a);
                acc[i][0] = ffma2(aa, b2.x, acc[i][0]);
                acc[i][1] = ffma2(aa, b2.y, acc[i][1]);
            }
        }
        __syncthreads();
    }

#pragma unroll
    for (int i = 0; i < 4; i++) {
        float2 r01 = upk2(acc[i][0]);
        float2 r23 = upk2(acc[i][1]);
        float4 o;
        o.x = fmaxf(r01.x, 0.f);
        o.y = fmaxf(r01.y, 0.f);
        o.z = fmaxf(r23.x, 0.f);
        o.w = fmaxf(r23.y, 0.f);
        *(float4*)&out[(size_t)(r0 + ty * 4 + i) * 512 + coff + c0 + tx * 4] = o;
    }
}

extern "C" void kernel_launch(void* const* d_in, const int* in_sizes, int n_in,
                              void* d_out, int out_size)
{
    const float* self_vecs    = (const float*)d_in[0];
    const float* neigh_vecs   = (const float*)d_in[1];
    const float* link_vecs    = (const float*)d_in[2];
    const float* select_probs = (const float*)d_in[3];
    const float* g_self_w     = (const float*)d_in[4];
    const float* g_neigh_w    = (const float*)d_in[5];
    const float* g_link_w     = (const float*)d_in[6];
    const float* W_link       = (const float*)d_in[7];
    const float* W_self       = (const float*)d_in[8];
    const float* W_neigh      = (const float*)d_in[9];
    float* out = (float*)d_out;

    static int attr_set = 0;
    if (!attr_set) {
        cudaFuncSetAttribute(mma_agg_kernel,
                             cudaFuncAttributeMaxDynamicSharedMemorySize, SMEM_TOTAL);
        attr_set = 1;
    }

    conv_w_kernel<<<32, 256>>>(W_link);
    ts_kernel<<<64, 256>>>(self_vecs, g_self_w);

    mma_agg_kernel<<<NCTA, 256, SMEM_TOTAL>>>(neigh_vecs, link_vecs, select_probs,
                                              g_neigh_w, g_link_w);

    dim3 g(NN / 64, 256 / 64);
    gemm_relu_kernel<<<g, 256>>>(self_vecs, W_self, out, 0, 0);
    gemm_relu_kernel<<<g, 256>>>(nullptr, W_neigh, out, 256, 1);
}

// round 14
// speedup vs baseline: 2.0810x; 1.2597x over previous
#include <cuda_runtime.h>
#include <cuda_bf16.h>
#include <cstdint>

#define NN 16384
#define KN 25
#define DD 256
#define LL 64
#define NPC 2                   // nodes per CTA
#define ROWS (NPC * KN)         // 50
#define MM 64                   // padded MMA M
#define NCTA (NN / NPC)         // 8192 (exact)
#define AST 68                  // A smem row stride in u32 (68 % 32 == 4 -> conflict-free frags)

// device scratch (no allocation allowed)
__device__ float g_expected[NN * DD];
__device__ uint2 g_Bfrag[DD * 8 * 4];   // [n][kk][tig] = {B[8kk+tig][n], B[8kk+tig+4][n]} as tf32
__device__ float g_ts[NN];

typedef unsigned int uint;
typedef unsigned long long ull;

// ---------------- smem layout (byte offsets in dynamic smem) ---------------
#define NEIGH_OFF   0           // 50*256*4  = 51200
#define A_OFF       51200       // 64*68*4   = 17408 (tf32)
#define DBUF_OFF    68608       // 32*260*4  = 33280
#define EXP_OFF     101888      // 2*256*4   = 2048
#define TLINK_OFF   103936      // 64*4
#define TNEIGH_OFF  104192      // 64*4
#define WK_OFF      104448      // 64*4
#define GNW_OFF     104704      // 256*4
#define GLW_OFF     105728      // 64*4
#define SMEM_TOTAL  105984      // ~103.5 KB -> 2 CTAs/SM

__device__ __forceinline__ uint tf32r(float x) {   // round-to-nearest tf32
    uint r; asm("cvt.rna.tf32.f32 %0, %1;" : "=r"(r) : "f"(x)); return r;
}
__device__ __forceinline__ float sigm_fast(float x) {  // 1 MUFU (tanh.approx)
    float th;
    asm("tanh.approx.f32 %0, %1;" : "=f"(th) : "f"(0.5f * x));
    return fmaf(0.5f, th, 0.5f);
}
// m16n8k8 tf32 mma, f32 accum (base-target PTX, sm_80+)
__device__ __forceinline__ void mma_tf32(float* c, const uint* a, uint b0, uint b1) {
    asm volatile(
        "mma.sync.aligned.m16n8k8.row.col.f32.tf32.tf32.f32 "
        "{%0,%1,%2,%3}, {%4,%5,%6,%7}, {%8,%9}, {%0,%1,%2,%3};"
        : "+f"(c[0]), "+f"(c[1]), "+f"(c[2]), "+f"(c[3])
        : "r"(a[0]), "r"(a[1]), "r"(a[2]), "r"(a[3]), "r"(b0), "r"(b1));
}
__device__ __forceinline__ uint smem_u32(const void* p) {
    uint a; asm("{ .reg .u64 t; cvta.to.shared.u64 t, %1; cvt.u32.u64 %0, t; }"
                : "=r"(a) : "l"(p));
    return a;
}
// fire-and-forget 16B global->shared copy (no dest registers, deep MLP)
__device__ __forceinline__ void cp_async16(uint smem_addr, const void* gptr) {
    asm volatile("cp.async.cg.shared.global [%0], [%1], 16;"
                 :: "r"(smem_addr), "l"(gptr) : "memory");
}
#define CP_COMMIT() asm volatile("cp.async.commit_group;" ::: "memory")
#define CP_WAIT0()  asm volatile("cp.async.wait_group 0;" ::: "memory")

// ---------------------------------------------------------------------------
// Precursor 1: pre-pack W_link into tf32 B-fragments in mma lane order.
// ---------------------------------------------------------------------------
__global__ void conv_w_kernel(const float* __restrict__ W_link) {
    int idx = blockIdx.x * 256 + threadIdx.x;   // 0..8191
    int n   = idx >> 5;
    int kk  = (idx >> 2) & 7;
    int tig = idx & 3;
    int l0  = 8 * kk + tig;
    uint2 v;
    v.x = tf32r(W_link[l0 * DD + n]);
    v.y = tf32r(W_link[(l0 + 4) * DD + n]);
    g_Bfrag[idx] = v;
}

// Precursor 2: g_ts[n] = self_vecs[n] . g_self_w
__global__ void ts_kernel(const float* __restrict__ self_vecs,
                          const float* __restrict__ g_self_w) {
    int warp = (blockIdx.x * 256 + threadIdx.x) >> 5;   // 512 warps
    int lane = threadIdx.x & 31;
    for (int n = warp; n < NN; n += 512) {
        float s = 0.f;
#pragma unroll
        for (int q = 0; q < 8; q++) {
            int d = lane + 32 * q;
            s = fmaf(self_vecs[n * DD + d], g_self_w[d], s);
        }
#pragma unroll
        for (int o = 16; o > 0; o >>= 1) s += __shfl_xor_sync(0xffffffffu, s, o);
        if (lane == 0) g_ts[n] = s;
    }
}

// ---------------------------------------------------------------------------
// Kernel A: R10 structure with the missing barrier restored.
//   1. neigh tile streamed via cp.async (no LDG->STS register chains)
//   2. __syncthreads so glw_s/gnw_s are visible BEFORE tlink staging (R10 bug)
//   3. tf32 MMA (needs only link+W_link) runs WHILE neigh is in flight
//   4. wait, gate dots, wk, epilogue (proven R9 math)
// ---------------------------------------------------------------------------
__global__ __launch_bounds__(256, 2) void mma_agg_kernel(
    const float* __restrict__ neigh_vecs,
    const float* __restrict__ link_vecs,
    const float* __restrict__ select_probs,
    const float* __restrict__ g_neigh_w,
    const float* __restrict__ g_link_w)
{
    extern __shared__ char sm[];
    const uint sb  = smem_u32(sm);
    const int t    = threadIdx.x;
    const int wid  = t >> 5;
    const int lane = t & 31;
    const int g8   = lane >> 2;     // mma groupID (0..7)
    const int tig  = lane & 3;      // thread-in-group
    const int b    = blockIdx.x;

    float*  neigh_s  = (float*)(sm + NEIGH_OFF);
    uint*   Asm      = (uint*)(sm + A_OFF);
    float*  dbuf     = (float*)(sm + DBUF_OFF);
    float*  exp_s    = (float*)(sm + EXP_OFF);
    float*  tlink_s  = (float*)(sm + TLINK_OFF);
    float*  tneigh_s = (float*)(sm + TNEIGH_OFF);
    float*  wk_s     = (float*)(sm + WK_OFF);
    float*  gnw_s    = (float*)(sm + GNW_OFF);
    float*  glw_s    = (float*)(sm + GLW_OFF);

    // step 0: issue neigh stream FIRST (fire-and-forget, covers kernel front)
    {
        const float4* src = (const float4*)(neigh_vecs + (long)b * ROWS * DD);
        for (int idx = t; idx < (ROWS * DD) / 4; idx += 256)
            cp_async16(sb + NEIGH_OFF + idx * 16, src + idx);
        CP_COMMIT();
    }

    // step 0b: small vectors + zero init
    gnw_s[t] = g_neigh_w[t];
    if (t < LL) glw_s[t] = g_link_w[t];
    if (t < MM) wk_s[t] = 0.f;
    exp_s[t] = 0.f; exp_s[256 + t] = 0.f;
    __syncthreads();   // <-- THE FIX: glw_s must be visible before step 1 reads it

    // step 1: stage A as tf32 [64, AST] + tlink partial dots (link is small)
    {
        int r = t >> 2, q = t & 3;              // row, 16-elem quarter
        bool valid = r < ROWS;
        const float4* src = (const float4*)(link_vecs + ((long)b * ROWS + r) * LL + 16 * q);
        const float4 z4 = make_float4(0.f, 0.f, 0.f, 0.f);
        float dl = 0.f;
#pragma unroll
        for (int u = 0; u < 4; u++) {
            float4 x = valid ? src[u] : z4;
            uint4 c4 = make_uint4(tf32r(x.x), tf32r(x.y), tf32r(x.z), tf32r(x.w));
            *(uint4*)&Asm[r * AST + 16 * q + 4 * u] = c4;
            int lb = 16 * q + 4 * u;
            dl = fmaf(x.x, glw_s[lb],     dl);
            dl = fmaf(x.y, glw_s[lb + 1], dl);
            dl = fmaf(x.z, glw_s[lb + 2], dl);
            dl = fmaf(x.w, glw_s[lb + 3], dl);
        }
        dl += __shfl_xor_sync(0xffffffffu, dl, 1);
        dl += __shfl_xor_sync(0xffffffffu, dl, 2);
        if (q == 0 && valid) tlink_s[r] = dl;
    }
    __syncthreads();   // Asm visible to all warps for the MMA

    // step 2: MMA (needs only Asm + g_Bfrag) — neigh stream still in flight
    float acc[4][4][4];
#pragma unroll
    for (int mi = 0; mi < 4; mi++)
#pragma unroll
        for (int ni = 0; ni < 4; ni++)
#pragma unroll
            for (int j = 0; j < 4; j++) acc[mi][ni][j] = 0.f;

#pragma unroll
    for (int kk = 0; kk < 8; kk++) {
        uint af[4][4];
#pragma unroll
        for (int mi = 0; mi < 4; mi++) {
            int e = (16 * mi + g8) * AST + 8 * kk + tig;
            af[mi][0] = Asm[e];
            af[mi][1] = Asm[e + 8 * AST];
            af[mi][2] = Asm[e + 4];
            af[mi][3] = Asm[e + 8 * AST + 4];
        }
#pragma unroll
        for (int ni = 0; ni < 4; ni++) {
            int n = 32 * wid + 8 * ni + g8;           // B col (output d)
            uint2 bb = g_Bfrag[(n * 8 + kk) * 4 + tig];
#pragma unroll
            for (int mi = 0; mi < 4; mi++)
                mma_tf32(acc[mi][ni], af[mi], bb.x, bb.y);
        }
    }

    // step 3: neigh must be resident now
    CP_WAIT0();
    __syncthreads();

    // step 4: gate — trans_neigh warp-task dots, then wk
    for (int task = wid; task < ROWS; task += 8) {
        float s = 0.f;
#pragma unroll
        for (int q = 0; q < 8; q++) {
            int d = lane + 32 * q;
            s = fmaf(neigh_s[task * DD + d], gnw_s[d], s);
        }
#pragma unroll
        for (int o = 16; o > 0; o >>= 1) s += __shfl_xor_sync(0xffffffffu, s, o);
        if (lane == 0) tneigh_s[task] = s;
    }
    __syncthreads();
    if (t < ROWS) {
        int node = t / KN, k = t - node * KN;
        int n = b * NPC + node;
        float r  = g_ts[n] + tneigh_s[t] + tlink_s[t];
        float gt = 1.f / (1.f + __expf(-r));
        wk_s[t]  = gt / (select_probs[n * KN + k] * (float)KN);
    }
    __syncthreads();

    // step 5: epilogue in two 32-row chunks (identical to proven R9)
#pragma unroll
    for (int c = 0; c < 2; c++) {
#pragma unroll
        for (int mi = 0; mi < 4; mi++) {
            if ((mi >> 1) == c) {
                int mm2  = mi & 1;
                int row0 = 16 * mi + g8;
                float w0 = wk_s[row0], w1 = wk_s[row0 + 8];
#pragma unroll
                for (int ni = 0; ni < 4; ni++) {
                    int col = 32 * wid + 8 * ni + 2 * tig;
                    float2 v0, v1;
                    v0.x = sigm_fast(acc[mi][ni][0]) * w0;
                    v0.y = sigm_fast(acc[mi][ni][1]) * w0;
                    v1.x = sigm_fast(acc[mi][ni][2]) * w1;
                    v1.y = sigm_fast(acc[mi][ni][3]) * w1;
                    *(float2*)&dbuf[(16 * mm2 + g8) * 260 + col]     = v0;
                    *(float2*)&dbuf[(16 * mm2 + g8 + 8) * 260 + col] = v1;
                }
            }
        }
        __syncthreads();
        int r0 = 32 * c;
#pragma unroll
        for (int i = 0; i < NPC; i++) {
            int lo = KN * i > r0 ? KN * i : r0;
            int hi = KN * i + KN < r0 + 32 ? KN * i + KN : r0 + 32;
            float a = 0.f;
            for (int j = lo; j < hi; j++)
                a = fmaf(dbuf[(j - r0) * 260 + t], neigh_s[j * DD + t], a);
            exp_s[i * DD + t] += a;
        }
        __syncthreads();
    }

    // step 6: write expected
#pragma unroll
    for (int i = 0; i < NPC; i++)
        g_expected[((long)b * NPC + i) * DD + t] = exp_s[i * DD + t];
}

// ---------------------------------------------------------------------------
// Kernel B: out[:, coff:coff+256] = relu(A @ W)  (unchanged, proven)
// ---------------------------------------------------------------------------
__device__ __forceinline__ ull pk2(float lo, float hi) {
    ull r; asm("mov.b64 %0, {%1, %2};" : "=l"(r) : "f"(lo), "f"(hi)); return r;
}
__device__ __forceinline__ float2 upk2(ull v) {
    float2 f; asm("mov.b64 {%0, %1}, %2;" : "=f"(f.x), "=f"(f.y) : "l"(v)); return f;
}
__device__ __forceinline__ ull ffma2(ull a, ull b, ull c) {
    ull d; asm("fma.rn.f32x2 %0, %1, %2, %3;" : "=l"(d) : "l"(a), "l"(b), "l"(c)); return d;
}

__global__ __launch_bounds__(256) void gemm_relu_kernel(
    const float* __restrict__ A_in,
    const float* __restrict__ W,
    float* __restrict__ out,
    int coff, int use_expected)
{
    const float* __restrict__ A = use_expected ? (const float*)g_expected : A_in;

    __shared__ float As[64][32];
    __shared__ alignas(16) float Ws[32][64];

    const int tid = threadIdx.x;
    const int tx  = tid & 15;
    const int ty  = tid >> 4;
    const int r0  = blockIdx.x * 64;
    const int c0  = blockIdx.y * 64;

    ull acc[4][2];
#pragma unroll
    for (int i = 0; i < 4; i++) { acc[i][0] = 0ull; acc[i][1] = 0ull; }

    for (int kb = 0; kb < DD; kb += 32) {
#pragma unroll
        for (int u = 0; u < 2; u++) {
            int idx = tid + u * 256;
            int m = idx >> 3, q = idx & 7;
            *(float4*)&As[m][q * 4] =
                *(const float4*)&A[(size_t)(r0 + m) * DD + kb + q * 4];
        }
#pragma unroll
        for (int u = 0; u < 2; u++) {
            int idx = tid + u * 256;
            int kk = idx >> 4, q = idx & 15;
            *(float4*)&Ws[kk][q * 4] =
                *(const float4*)&W[(size_t)(kb + kk) * DD + c0 + q * 4];
        }
        __syncthreads();
#pragma unroll
        for (int kk = 0; kk < 32; kk++) {
            ulonglong2 b2 = *(const ulonglong2*)&Ws[kk][tx * 4];
#pragma unroll
            for (int i = 0; i < 4; i++) {
                float a = As[ty * 4 + i][kk];
                ull aa = pk2(a, a);
                acc[i][0] = ffma2(aa, b2.x, acc[i][0]);
                acc[i][1] = ffma2(aa, b2.y, acc[i][1]);
            }
        }
        __syncthreads();
    }

#pragma unroll
    for (int i = 0; i < 4; i++) {
        float2 r01 = upk2(acc[i][0]);
        float2 r23 = upk2(acc[i][1]);
        float4 o;
        o.x = fmaxf(r01.x, 0.f);
        o.y = fmaxf(r01.y, 0.f);
        o.z = fmaxf(r23.x, 0.f);
        o.w = fmaxf(r23.y, 0.f);
        *(float4*)&out[(size_t)(r0 + ty * 4 + i) * 512 + coff + c0 + tx * 4] = o;
    }
}

extern "C" void kernel_launch(void* const* d_in, const int* in_sizes, int n_in,
                              void* d_out, int out_size)
{
    const float* self_vecs    = (const float*)d_in[0];
    const float* neigh_vecs   = (const float*)d_in[1];
    const float* link_vecs    = (const float*)d_in[2];
    const float* select_probs = (const float*)d_in[3];
    const float* g_self_w     = (const float*)d_in[4];
    const float* g_neigh_w    = (const float*)d_in[5];
    const float* g_link_w     = (const float*)d_in[6];
    const float* W_link       = (const float*)d_in[7];
    const float* W_self       = (const float*)d_in[8];
    const float* W_neigh      = (const float*)d_in[9];
    float* out = (float*)d_out;

    static int attr_set = 0;
    if (!attr_set) {
        cudaFuncSetAttribute(mma_agg_kernel,
                             cudaFuncAttributeMaxDynamicSharedMemorySize, SMEM_TOTAL);
        attr_set = 1;
    }

    conv_w_kernel<<<32, 256>>>(W_link);
    ts_kernel<<<64, 256>>>(self_vecs, g_self_w);

    mma_agg_kernel<<<NCTA, 256, SMEM_TOTAL>>>(neigh_vecs, link_vecs, select_probs,
                                              g_neigh_w, g_link_w);

    dim3 g(NN / 64, 256 / 64);
    gemm_relu_kernel<<<g, 256>>>(self_vecs, W_self, out, 0, 0);
    gemm_relu_kernel<<<g, 256>>>(nullptr, W_neigh, out, 256, 1);
}